// round 1
// baseline (speedup 1.0000x reference)
#include <cuda_runtime.h>
#include <cstdint>

// Quantizer: zq[t] = codebook[argmin_k ||ze[t] - codebook[k]||^2]
// Shapes: ze [524288, 64] fp32, codebook [512, 64] fp32, out [524288, 64] fp32.
//
// Strategy (round 1, fp32-exact):
//  - codebook (128 KB) + ||c||^2 (2 KB) in dynamic SMEM, 1 CTA/SM.
//  - dist_k = ||c_k||^2 - 2 * <ze, c_k>   (||ze||^2 dropped: argmin-invariant)
//  - packed fma.rn.f32x2 (SASS FFMA2) for 2x fp32 FMA throughput.
//  - broadcast LDS.128 of codebook rows (all lanes read same code -> no conflicts).
//  - strict < comparison matches jnp.argmin first-index tie-breaking.

#define DQ      64
#define KCODES  512
#define THREADS 256
#define BLOCKS  152
#define SMEM_BYTES ((KCODES * DQ + KCODES) * 4)

// Packed dual-FMA: {dx,dy} += {ax,ay} * {bx,by} elementwise (fp32x2).
__device__ __forceinline__ void ffma2(float& dx, float& dy,
                                      float ax, float ay,
                                      float bx, float by) {
    asm("{\n\t"
        ".reg .b64 ra, rb, rd;\n\t"
        "mov.b64 rd, {%0, %1};\n\t"
        "mov.b64 ra, {%2, %3};\n\t"
        "mov.b64 rb, {%4, %5};\n\t"
        "fma.rn.f32x2 rd, ra, rb, rd;\n\t"
        "mov.b64 {%0, %1}, rd;\n\t"
        "}"
        : "+f"(dx), "+f"(dy)
        : "f"(ax), "f"(ay), "f"(bx), "f"(by));
}

__global__ __launch_bounds__(THREADS, 1)
void vq_argmin_gather_kernel(const float* __restrict__ ze,
                             const float* __restrict__ cb,
                             float* __restrict__ out,
                             int n_tokens) {
    extern __shared__ float smem[];
    float* scb   = smem;                 // [KCODES * DQ]
    float* snorm = smem + KCODES * DQ;   // [KCODES]

    // Cooperative load of the codebook into SMEM (float4 = 16B chunks).
    {
        const float4* src = reinterpret_cast<const float4*>(cb);
        float4* dst = reinterpret_cast<float4*>(scb);
        for (int i = threadIdx.x; i < (KCODES * DQ) / 4; i += THREADS)
            dst[i] = src[i];
    }
    __syncthreads();

    // Precompute ||c_k||^2.
    for (int k = threadIdx.x; k < KCODES; k += THREADS) {
        const float* row = scb + k * DQ;
        float s0 = 0.f, s1 = 0.f, s2 = 0.f, s3 = 0.f;
        #pragma unroll
        for (int d = 0; d < DQ; d += 4) {
            s0 += row[d + 0] * row[d + 0];
            s1 += row[d + 1] * row[d + 1];
            s2 += row[d + 2] * row[d + 2];
            s3 += row[d + 3] * row[d + 3];
        }
        snorm[k] = (s0 + s1) + (s2 + s3);
    }
    __syncthreads();

    const int tid    = blockIdx.x * THREADS + threadIdx.x;
    const int stride = gridDim.x * THREADS;

    for (int t = tid; t < n_tokens; t += stride) {
        // Load this token's ze row (64 floats) into registers.
        const float4* zp = reinterpret_cast<const float4*>(ze + (size_t)t * DQ);
        float4 zv[16];
        #pragma unroll
        for (int i = 0; i < 16; i++) zv[i] = zp[i];

        float best_d = 3.4e38f;
        int   best_k = 0;

        #pragma unroll 2
        for (int k = 0; k < KCODES; k++) {
            const float4* crow = reinterpret_cast<const float4*>(scb + k * DQ);
            // 4 independent packed accumulators (cover FFMA lat=4 @ rt=2).
            float a0x = 0.f, a0y = 0.f, a1x = 0.f, a1y = 0.f;
            float a2x = 0.f, a2y = 0.f, a3x = 0.f, a3y = 0.f;
            #pragma unroll
            for (int i = 0; i < 16; i += 2) {
                float4 c0 = crow[i];
                float4 c1 = crow[i + 1];
                ffma2(a0x, a0y, zv[i].x,     zv[i].y,     c0.x, c0.y);
                ffma2(a1x, a1y, zv[i].z,     zv[i].w,     c0.z, c0.w);
                ffma2(a2x, a2y, zv[i + 1].x, zv[i + 1].y, c1.x, c1.y);
                ffma2(a3x, a3y, zv[i + 1].z, zv[i + 1].w, c1.z, c1.w);
            }
            float dot = ((a0x + a1x) + (a2x + a3x)) + ((a0y + a1y) + (a2y + a3y));
            float dist = snorm[k] - 2.0f * dot;
            if (dist < best_d) { best_d = dist; best_k = k; }
        }

        // Gather: copy the winning codebook row from SMEM to out.
        const float4* win = reinterpret_cast<const float4*>(scb + best_k * DQ);
        float4* op = reinterpret_cast<float4*>(out + (size_t)t * DQ);
        #pragma unroll
        for (int i = 0; i < 16; i++) op[i] = win[i];
    }
}

extern "C" void kernel_launch(void* const* d_in, const int* in_sizes, int n_in,
                              void* d_out, int out_size) {
    const float* ze = (const float*)d_in[0];
    const float* cb = (const float*)d_in[1];
    float* out = (float*)d_out;
    const int n_tokens = in_sizes[0] / DQ;

    cudaFuncSetAttribute(vq_argmin_gather_kernel,
                         cudaFuncAttributeMaxDynamicSharedMemorySize, SMEM_BYTES);
    vq_argmin_gather_kernel<<<BLOCKS, THREADS, SMEM_BYTES>>>(ze, cb, out, n_tokens);
}

// round 2
// speedup vs baseline: 1.2796x; 1.2796x over previous
#include <cuda_runtime.h>
#include <cstdint>

// Quantizer: zq[t] = codebook[argmin_k ||ze[t] - codebook[k]||^2]
// ze [524288, 64] fp32, codebook [512, 64] fp32, out [524288, 64] fp32.
//
// Round 2: amortize codebook SMEM loads across 2 tokens per thread.
// R1 showed L1/shared = 86% (binding), fma = 44%. Halving LDS-per-FMA
// moves the kernel to the scalar FFMA2 roofline (~440 us floor).
//  - dist_k = ||c_k||^2 - 2 * <ze, c_k>  (||ze||^2 dropped: argmin-invariant)
//  - packed fma.rn.f32x2 / add.rn.f32x2 for 2x fp32 throughput
//  - strict < keeps jnp.argmin first-index tie-break; fp32-exact (R1: rel_err=0)

#define DQ      64
#define KCODES  512
#define THREADS 256
#define BLOCKS  152
#define TOK     2
#define SMEM_BYTES ((KCODES * DQ + KCODES) * 4)

__device__ __forceinline__ void ffma2(float& dx, float& dy,
                                      float ax, float ay,
                                      float bx, float by) {
    asm("{\n\t"
        ".reg .b64 ra, rb, rd;\n\t"
        "mov.b64 rd, {%0, %1};\n\t"
        "mov.b64 ra, {%2, %3};\n\t"
        "mov.b64 rb, {%4, %5};\n\t"
        "fma.rn.f32x2 rd, ra, rb, rd;\n\t"
        "mov.b64 {%0, %1}, rd;\n\t"
        "}"
        : "+f"(dx), "+f"(dy)
        : "f"(ax), "f"(ay), "f"(bx), "f"(by));
}

__device__ __forceinline__ void fadd2(float& dx, float& dy,
                                      float ax, float ay,
                                      float bx, float by) {
    asm("{\n\t"
        ".reg .b64 ra, rb, rd;\n\t"
        "mov.b64 ra, {%2, %3};\n\t"
        "mov.b64 rb, {%4, %5};\n\t"
        "add.rn.f32x2 rd, ra, rb;\n\t"
        "mov.b64 {%0, %1}, rd;\n\t"
        "}"
        : "=f"(dx), "=f"(dy)
        : "f"(ax), "f"(ay), "f"(bx), "f"(by));
}

__global__ __launch_bounds__(THREADS, 1)
void vq_argmin_gather_kernel(const float* __restrict__ ze,
                             const float* __restrict__ cb,
                             float* __restrict__ out,
                             int n_tokens) {
    extern __shared__ float smem[];
    float* scb   = smem;                 // [KCODES * DQ]
    float* snorm = smem + KCODES * DQ;   // [KCODES]

    // Cooperative codebook load (float4 chunks).
    {
        const float4* src = reinterpret_cast<const float4*>(cb);
        float4* dst = reinterpret_cast<float4*>(scb);
        for (int i = threadIdx.x; i < (KCODES * DQ) / 4; i += THREADS)
            dst[i] = src[i];
    }
    __syncthreads();

    // Precompute ||c_k||^2.
    for (int k = threadIdx.x; k < KCODES; k += THREADS) {
        const float* row = scb + k * DQ;
        float s0 = 0.f, s1 = 0.f, s2 = 0.f, s3 = 0.f;
        #pragma unroll
        for (int d = 0; d < DQ; d += 4) {
            s0 += row[d + 0] * row[d + 0];
            s1 += row[d + 1] * row[d + 1];
            s2 += row[d + 2] * row[d + 2];
            s3 += row[d + 3] * row[d + 3];
        }
        snorm[k] = (s0 + s1) + (s2 + s3);
    }
    __syncthreads();

    const int gid    = blockIdx.x * THREADS + threadIdx.x;
    const int stride = gridDim.x * THREADS;
    const int n_pairs = n_tokens / TOK;

    for (int p = gid; p < n_pairs; p += stride) {
        const int t0 = p * TOK;

        // Two ze rows in registers (2 x 64 floats).
        float4 zv[TOK][16];
        #pragma unroll
        for (int j = 0; j < TOK; j++) {
            const float4* zp = reinterpret_cast<const float4*>(ze + (size_t)(t0 + j) * DQ);
            #pragma unroll
            for (int i = 0; i < 16; i++) zv[j][i] = zp[i];
        }

        float best_d[TOK];
        int   best_k[TOK];
        #pragma unroll
        for (int j = 0; j < TOK; j++) { best_d[j] = 3.4e38f; best_k[j] = 0; }

        #pragma unroll 2
        for (int k = 0; k < KCODES; k++) {
            const float4* crow = reinterpret_cast<const float4*>(scb + k * DQ);
            const float nrm = snorm[k];

            // 4 packed accumulator pairs per token (8 indep chains total).
            float ax[TOK][4], ay[TOK][4];
            #pragma unroll
            for (int j = 0; j < TOK; j++)
                #pragma unroll
                for (int q = 0; q < 4; q++) { ax[j][q] = 0.f; ay[j][q] = 0.f; }

            #pragma unroll
            for (int i = 0; i < 16; i += 2) {
                float4 c0 = crow[i];
                float4 c1 = crow[i + 1];
                #pragma unroll
                for (int j = 0; j < TOK; j++) {
                    ffma2(ax[j][0], ay[j][0], zv[j][i].x,     zv[j][i].y,     c0.x, c0.y);
                    ffma2(ax[j][1], ay[j][1], zv[j][i].z,     zv[j][i].w,     c0.z, c0.w);
                    ffma2(ax[j][2], ay[j][2], zv[j][i + 1].x, zv[j][i + 1].y, c1.x, c1.y);
                    ffma2(ax[j][3], ay[j][3], zv[j][i + 1].z, zv[j][i + 1].w, c1.z, c1.w);
                }
            }

            #pragma unroll
            for (int j = 0; j < TOK; j++) {
                // Packed reduction tree: 2 packed adds + 1 packed + cross add.
                float sx, sy, tx, ty, ux, uy;
                fadd2(sx, sy, ax[j][0], ay[j][0], ax[j][1], ay[j][1]);
                fadd2(tx, ty, ax[j][2], ay[j][2], ax[j][3], ay[j][3]);
                fadd2(ux, uy, sx, sy, tx, ty);
                float dot = ux + uy;
                float dist = fmaf(-2.0f, dot, nrm);
                if (dist < best_d[j]) { best_d[j] = dist; best_k[j] = k; }
            }
        }

        // Gather winning rows from SMEM to out.
        #pragma unroll
        for (int j = 0; j < TOK; j++) {
            const float4* win = reinterpret_cast<const float4*>(scb + best_k[j] * DQ);
            float4* op = reinterpret_cast<float4*>(out + (size_t)(t0 + j) * DQ);
            #pragma unroll
            for (int i = 0; i < 16; i++) op[i] = win[i];
        }
    }
}

extern "C" void kernel_launch(void* const* d_in, const int* in_sizes, int n_in,
                              void* d_out, int out_size) {
    const float* ze = (const float*)d_in[0];
    const float* cb = (const float*)d_in[1];
    float* out = (float*)d_out;
    const int n_tokens = in_sizes[0] / DQ;

    cudaFuncSetAttribute(vq_argmin_gather_kernel,
                         cudaFuncAttributeMaxDynamicSharedMemorySize, SMEM_BYTES);
    vq_argmin_gather_kernel<<<BLOCKS, THREADS, SMEM_BYTES>>>(ze, cb, out, n_tokens);
}

// round 4
// speedup vs baseline: 1.2952x; 1.0122x over previous
#include <cuda_runtime.h>
#include <cuda_fp16.h>
#include <cstdint>

// VQ quantizer via legacy mma.sync (HMMA) + fused argmin + exact rescue.
// (tcgen05 is unavailable: harness compiles through compute_103 non-'a' PTX.)
//
// dist_k = ||c_k||^2 - 2*<z,c_k>.  <z,c> via fp16 3-term split GEMM (K=192):
//   seg0: z_hi * c_hi,  seg1: z_hi * c_lo,  seg2: z_lo * c_hi   (fp32 accum)
// err(dist) <~ 3e-4. Tokens with top-2 gap < DELTA=2e-3 get exact fp32
// rescore; top-3 gap < DELTA triggers full exact scan (ultra-rare).
//
// A (z hi/lo) lives in registers, reused across all 512 codes.
// B (codebook hi|lo fp16) pre-split by a prep kernel into a padded layout
// (row stride 272B -> conflict-free ldmatrix), copied to SMEM per CTA.

#define DQ        64
#define KC        512
#define ROWB      272                     // bytes per packed code row: hi128|lo128|pad16
#define PACK_BYTES (KC * ROWB)            // 139264
#define THREADS   256
#define MROWS     256                     // tokens per CTA (8 warps x 32 rows)
#define DELTA     2e-3f
#define SMEM_TOTAL (PACK_BYTES + KC * 4)  // + cnorm

__device__ __align__(16) unsigned char g_cbpack[PACK_BYTES];
__device__ float g_cnorm[KC];

// ---------------- helpers ----------------

__device__ __forceinline__ uint32_t smem_u32(const void* p) {
    uint32_t a;
    asm("{ .reg .u64 t; cvta.to.shared.u64 t, %1; cvt.u32.u64 %0, t; }" : "=r"(a) : "l"(p));
    return a;
}

__device__ __forceinline__ uint32_t pack2(__half a, __half b) {
    __half2 h = __halves2half2(a, b);
    return *reinterpret_cast<uint32_t*>(&h);
}

#define LDSM4(r0, r1, r2, r3, addr)                                         \
    asm volatile("ldmatrix.sync.aligned.m8n8.x4.shared.b16 {%0,%1,%2,%3}, [%4];" \
        : "=r"(r0), "=r"(r1), "=r"(r2), "=r"(r3) : "r"(addr))

#define MMA16816(c0, c1, c2, c3, a0, a1, a2, a3, b0, b1)                    \
    asm volatile("mma.sync.aligned.m16n8k16.row.col.f32.f16.f16.f32 "       \
        "{%0,%1,%2,%3}, {%4,%5,%6,%7}, {%8,%9}, {%0,%1,%2,%3};"             \
        : "+f"(c0), "+f"(c1), "+f"(c2), "+f"(c3)                            \
        : "r"(a0), "r"(a1), "r"(a2), "r"(a3), "r"(b0), "r"(b1))

__device__ __forceinline__ void insert3(float& d1, float& d2, float& d3,
                                        int& k1, int& k2, int& k3,
                                        float d, int k) {
    if (d < d3) {
        if (d < d2) {
            d3 = d2; k3 = k2;
            if (d < d1) { d2 = d1; k2 = k1; d1 = d; k1 = k; }
            else        { d2 = d;  k2 = k; }
        } else { d3 = d; k3 = k; }
    }
}

__device__ __forceinline__ float exact_dist(const float4* zv, const float* crow_f,
                                            float nrm) {
    const float4* crow = reinterpret_cast<const float4*>(crow_f);
    float s0 = 0.f, s1 = 0.f, s2 = 0.f, s3 = 0.f;
    #pragma unroll
    for (int i = 0; i < 16; i++) {
        float4 c = crow[i]; float4 z = zv[i];
        s0 = fmaf(z.x, c.x, s0); s1 = fmaf(z.y, c.y, s1);
        s2 = fmaf(z.z, c.z, s2); s3 = fmaf(z.w, c.w, s3);
    }
    return fmaf(-2.0f, (s0 + s1) + (s2 + s3), nrm);
}

// ---------------- prep: split codebook to fp16 hi|lo + norms ----------------

__global__ void prep_kernel(const float* __restrict__ cb) {
    const int k = threadIdx.x;
    if (k >= KC) return;
    const float4* row = reinterpret_cast<const float4*>(cb + (size_t)k * DQ);
    uint32_t* dst = reinterpret_cast<uint32_t*>(g_cbpack + (size_t)k * ROWB);
    float s0 = 0.f, s1 = 0.f, s2 = 0.f, s3 = 0.f;
    #pragma unroll
    for (int i = 0; i < 16; i++) {
        float4 f = row[i];
        s0 = fmaf(f.x, f.x, s0); s1 = fmaf(f.y, f.y, s1);
        s2 = fmaf(f.z, f.z, s2); s3 = fmaf(f.w, f.w, s3);
        __half hx = __float2half_rn(f.x), hy = __float2half_rn(f.y);
        __half hz = __float2half_rn(f.z), hw = __float2half_rn(f.w);
        // hi halves at u32 idx 2i, 2i+1 ; lo halves at 32+2i, 32+2i+1
        dst[2*i]       = pack2(hx, hy);
        dst[2*i + 1]   = pack2(hz, hw);
        dst[32 + 2*i]     = pack2(__float2half_rn(f.x - __half2float(hx)),
                                  __float2half_rn(f.y - __half2float(hy)));
        dst[32 + 2*i + 1] = pack2(__float2half_rn(f.z - __half2float(hz)),
                                  __float2half_rn(f.w - __half2float(hw)));
    }
    g_cnorm[k] = (s0 + s1) + (s2 + s3);
}

// ---------------- main ----------------

__global__ __launch_bounds__(THREADS, 1)
void vq_main(const float* __restrict__ ze,
             const float* __restrict__ cb,
             float* __restrict__ out) {
    extern __shared__ char smem[];
    float* scn = reinterpret_cast<float*>(smem + PACK_BYTES);

    // Copy packed codebook + norms to SMEM.
    {
        const uint4* src = reinterpret_cast<const uint4*>(g_cbpack);
        uint4* dst = reinterpret_cast<uint4*>(smem);
        for (int i = threadIdx.x; i < PACK_BYTES / 16; i += THREADS) dst[i] = src[i];
        for (int i = threadIdx.x; i < KC; i += THREADS) scn[i] = g_cnorm[i];
    }
    __syncthreads();

    const int tid  = threadIdx.x;
    const int w    = tid >> 5;
    const int lane = tid & 31;
    const int g    = lane >> 2;     // group id 0..7
    const int t    = lane & 3;      // thread in group
    const int row_base = blockIdx.x * MROWS + w * 32;

    // Build A fragments in registers: Ah/Al [m-tile][k-tile][reg]
    uint32_t Ah[2][4][4], Al[2][4][4];
    #pragma unroll
    for (int r4 = 0; r4 < 4; r4++) {
        const float* zr = ze + (size_t)(row_base + g + 8 * r4) * DQ;
        #pragma unroll
        for (int j = 0; j < 8; j++) {
            float2 f = *reinterpret_cast<const float2*>(zr + 2 * t + 8 * j);
            __half hx = __float2half_rn(f.x), hy = __float2half_rn(f.y);
            __half lx = __float2half_rn(f.x - __half2float(hx));
            __half ly = __float2half_rn(f.y - __half2float(hy));
            const int mt = r4 >> 1, kt = j >> 1, idx = 2 * (j & 1) + (r4 & 1);
            Ah[mt][kt][idx] = pack2(hx, hy);
            Al[mt][kt][idx] = pack2(lx, ly);
        }
    }

    // Per-row-slot running top-3 (slots: rows g, g+8, g+16, g+24)
    float td1[4], td2[4], td3[4];
    int   tk1[4], tk2[4], tk3[4];
    #pragma unroll
    for (int s = 0; s < 4; s++) {
        td1[s] = td2[s] = td3[s] = 3.4e38f;
        tk1[s] = tk2[s] = tk3[s] = 0;
    }

    const uint32_t smem_u = smem_u32(smem);
    // ldmatrix lane addressing: lanes 0-7 m0(n0..7,klo), 8-15 m1(n0..7,khi),
    // 16-23 m2(n8..15,klo), 24-31 m3(n8..15,khi)
    const int      brow = ((lane >> 4) & 1) * 8 + (lane & 7);
    const uint32_t koff = ((lane >> 3) & 1) * 16;

    #pragma unroll 1
    for (int c = 0; c < KC / 16; c++) {
        const int n0 = c * 16;
        const uint32_t bbase = smem_u + (uint32_t)(n0 + brow) * ROWB + koff;

        float acc[2][2][4];
        #pragma unroll
        for (int mt = 0; mt < 2; mt++)
            #pragma unroll
            for (int nt = 0; nt < 2; nt++)
                #pragma unroll
                for (int q = 0; q < 4; q++) acc[mt][nt][q] = 0.f;

        uint32_t B[4][4];
        // -------- c_hi: seg0 (z_hi) + seg2 (z_lo) --------
        #pragma unroll
        for (int kt = 0; kt < 4; kt++)
            LDSM4(B[kt][0], B[kt][1], B[kt][2], B[kt][3], bbase + kt * 32);
        #pragma unroll
        for (int kt = 0; kt < 4; kt++)
            #pragma unroll
            for (int mt = 0; mt < 2; mt++) {
                MMA16816(acc[mt][0][0], acc[mt][0][1], acc[mt][0][2], acc[mt][0][3],
                         Ah[mt][kt][0], Ah[mt][kt][1], Ah[mt][kt][2], Ah[mt][kt][3],
                         B[kt][0], B[kt][1]);
                MMA16816(acc[mt][1][0], acc[mt][1][1], acc[mt][1][2], acc[mt][1][3],
                         Ah[mt][kt][0], Ah[mt][kt][1], Ah[mt][kt][2], Ah[mt][kt][3],
                         B[kt][2], B[kt][3]);
            }
        #pragma unroll
        for (int kt = 0; kt < 4; kt++)
            #pragma unroll
            for (int mt = 0; mt < 2; mt++) {
                MMA16816(acc[mt][0][0], acc[mt][0][1], acc[mt][0][2], acc[mt][0][3],
                         Al[mt][kt][0], Al[mt][kt][1], Al[mt][kt][2], Al[mt][kt][3],
                         B[kt][0], B[kt][1]);
                MMA16816(acc[mt][1][0], acc[mt][1][1], acc[mt][1][2], acc[mt][1][3],
                         Al[mt][kt][0], Al[mt][kt][1], Al[mt][kt][2], Al[mt][kt][3],
                         B[kt][2], B[kt][3]);
            }
        // -------- c_lo: seg1 (z_hi) --------
        #pragma unroll
        for (int kt = 0; kt < 4; kt++)
            LDSM4(B[kt][0], B[kt][1], B[kt][2], B[kt][3], bbase + 128 + kt * 32);
        #pragma unroll
        for (int kt = 0; kt < 4; kt++)
            #pragma unroll
            for (int mt = 0; mt < 2; mt++) {
                MMA16816(acc[mt][0][0], acc[mt][0][1], acc[mt][0][2], acc[mt][0][3],
                         Ah[mt][kt][0], Ah[mt][kt][1], Ah[mt][kt][2], Ah[mt][kt][3],
                         B[kt][0], B[kt][1]);
                MMA16816(acc[mt][1][0], acc[mt][1][1], acc[mt][1][2], acc[mt][1][3],
                         Ah[mt][kt][0], Ah[mt][kt][1], Ah[mt][kt][2], Ah[mt][kt][3],
                         B[kt][2], B[kt][3]);
            }

        // -------- epilogue: dist + top-3 --------
        const float2 cn0 = *reinterpret_cast<const float2*>(&scn[n0 + 2 * t]);
        const float2 cn1 = *reinterpret_cast<const float2*>(&scn[n0 + 8 + 2 * t]);
        #pragma unroll
        for (int mt = 0; mt < 2; mt++)
            #pragma unroll
            for (int nt = 0; nt < 2; nt++) {
                const float cA = nt ? cn1.x : cn0.x;
                const float cB = nt ? cn1.y : cn0.y;
                const int colA = n0 + nt * 8 + 2 * t;
                const int sA = 2 * mt, sB = 2 * mt + 1;
                insert3(td1[sA], td2[sA], td3[sA], tk1[sA], tk2[sA], tk3[sA],
                        fmaf(-2.f, acc[mt][nt][0], cA), colA);
                insert3(td1[sA], td2[sA], td3[sA], tk1[sA], tk2[sA], tk3[sA],
                        fmaf(-2.f, acc[mt][nt][1], cB), colA + 1);
                insert3(td1[sB], td2[sB], td3[sB], tk1[sB], tk2[sB], tk3[sB],
                        fmaf(-2.f, acc[mt][nt][2], cA), colA);
                insert3(td1[sB], td2[sB], td3[sB], tk1[sB], tk2[sB], tk3[sB],
                        fmaf(-2.f, acc[mt][nt][3], cB), colA + 1);
            }
    }

    // Cross-lane merge: lanes 4g..4g+3 hold disjoint column slices of the
    // same 4 rows. Butterfly over xor 1, 2.
    #pragma unroll
    for (int xo = 1; xo <= 2; xo <<= 1) {
        #pragma unroll
        for (int s = 0; s < 4; s++) {
            float o1 = __shfl_xor_sync(0xFFFFFFFFu, td1[s], xo);
            float o2 = __shfl_xor_sync(0xFFFFFFFFu, td2[s], xo);
            float o3 = __shfl_xor_sync(0xFFFFFFFFu, td3[s], xo);
            int   q1 = __shfl_xor_sync(0xFFFFFFFFu, tk1[s], xo);
            int   q2 = __shfl_xor_sync(0xFFFFFFFFu, tk2[s], xo);
            int   q3 = __shfl_xor_sync(0xFFFFFFFFu, tk3[s], xo);
            insert3(td1[s], td2[s], td3[s], tk1[s], tk2[s], tk3[s], o1, q1);
            insert3(td1[s], td2[s], td3[s], tk1[s], tk2[s], tk3[s], o2, q2);
            insert3(td1[s], td2[s], td3[s], tk1[s], tk2[s], tk3[s], o3, q3);
        }
    }

    // Resolution: lane 4g+t owns slot t (row g + 8t).
    const int my_row = row_base + g + 8 * t;
    float rd1 = td1[t], rd2 = td2[t], rd3 = td3[t];
    int   rk1 = tk1[t], rk2 = tk2[t];
    int   kw = rk1;
    if (rd3 - rd1 < DELTA) {
        // full exact fp32 scan (ultra-rare)
        float4 zv[16];
        const float4* zp = reinterpret_cast<const float4*>(ze + (size_t)my_row * DQ);
        #pragma unroll
        for (int i = 0; i < 16; i++) zv[i] = zp[i];
        float best = 3.4e38f; int bk = 0;
        for (int k = 0; k < KC; k++) {
            const float d = exact_dist(zv, cb + (size_t)k * DQ, scn[k]);
            if (d < best) { best = d; bk = k; }
        }
        kw = bk;
    } else if (rd2 - rd1 < DELTA) {
        float4 zv[16];
        const float4* zp = reinterpret_cast<const float4*>(ze + (size_t)my_row * DQ);
        #pragma unroll
        for (int i = 0; i < 16; i++) zv[i] = zp[i];
        const float e1 = exact_dist(zv, cb + (size_t)rk1 * DQ, scn[rk1]);
        const float e2 = exact_dist(zv, cb + (size_t)rk2 * DQ, scn[rk2]);
        if (e2 < e1 || (e2 == e1 && rk2 < rk1)) kw = rk2;
    }

    // Coalesced gather/write: warp handles its 32 rows one at a time.
    #pragma unroll 1
    for (int r = 0; r < 32; r++) {
        const int src_lane = 4 * (r & 7) + (r >> 3);   // owner of warp-row r
        const int kk = __shfl_sync(0xFFFFFFFFu, kw, src_lane);
        const float2 v = reinterpret_cast<const float2*>(cb + (size_t)kk * DQ)[lane];
        reinterpret_cast<float2*>(out + (size_t)(row_base + r) * DQ)[lane] = v;
    }
}

extern "C" void kernel_launch(void* const* d_in, const int* in_sizes, int n_in,
                              void* d_out, int out_size) {
    const float* ze = (const float*)d_in[0];
    const float* cb = (const float*)d_in[1];
    float* out = (float*)d_out;
    const int n_tokens = in_sizes[0] / DQ;
    const int grid = n_tokens / MROWS;   // 2048

    prep_kernel<<<1, KC>>>(cb);
    cudaFuncSetAttribute(vq_main,
                         cudaFuncAttributeMaxDynamicSharedMemorySize, SMEM_TOTAL);
    vq_main<<<grid, THREADS, SMEM_TOTAL>>>(ze, cb, out);
}

// round 5
// speedup vs baseline: 2.4950x; 1.9263x over previous
#include <cuda_runtime.h>
#include <cuda_fp16.h>
#include <cstdint>

// VQ quantizer via legacy mma.sync (HMMA) + fused argmin + exact rescue.
// Round 5: 512-thread CTA (16 warps/SM, was 8) — occupancy was the binding
// constraint (issue=39%, occ=12.4%). Warp covers 16 rows (was 32), halving
// per-thread A regs (210 -> ~100) so 512 threads fit the register file.
//
// dist_k = ||c_k||^2 - 2*<z,c_k>.  <z,c> via fp16 3-term split (K=192):
//   seg0 z_hi*c_hi + seg2 z_lo*c_hi + seg1 z_hi*c_lo, fp32 accumulate.
// err(dist) <~ 3e-4; tokens with top-2 gap < DELTA=2e-3 get exact rescore,
// top-3 gap < DELTA -> full exact scan (ultra-rare). Proven rel_err=0.0.

#define DQ        64
#define KC        512
#define ROWB      272                     // packed code row: hi128|lo128|pad16
#define PACK_BYTES (KC * ROWB)            // 139264
#define THREADS   512
#define MROWS     256                     // tokens per CTA (16 warps x 16 rows)
#define DELTA     2e-3f
#define SMEM_TOTAL (PACK_BYTES + KC * 4)

__device__ __align__(16) unsigned char g_cbpack[PACK_BYTES];
__device__ float g_cnorm[KC];

// ---------------- helpers ----------------

__device__ __forceinline__ uint32_t smem_u32(const void* p) {
    uint32_t a;
    asm("{ .reg .u64 t; cvta.to.shared.u64 t, %1; cvt.u32.u64 %0, t; }" : "=r"(a) : "l"(p));
    return a;
}

__device__ __forceinline__ uint32_t pack2(__half a, __half b) {
    __half2 h = __halves2half2(a, b);
    return *reinterpret_cast<uint32_t*>(&h);
}

#define LDSM4(r0, r1, r2, r3, addr)                                         \
    asm volatile("ldmatrix.sync.aligned.m8n8.x4.shared.b16 {%0,%1,%2,%3}, [%4];" \
        : "=r"(r0), "=r"(r1), "=r"(r2), "=r"(r3) : "r"(addr))

#define MMA16816(c0, c1, c2, c3, a0, a1, a2, a3, b0, b1)                    \
    asm volatile("mma.sync.aligned.m16n8k16.row.col.f32.f16.f16.f32 "       \
        "{%0,%1,%2,%3}, {%4,%5,%6,%7}, {%8,%9}, {%0,%1,%2,%3};"             \
        : "+f"(c0), "+f"(c1), "+f"(c2), "+f"(c3)                            \
        : "r"(a0), "r"(a1), "r"(a2), "r"(a3), "r"(b0), "r"(b1))

__device__ __forceinline__ void insert3(float& d1, float& d2, float& d3,
                                        int& k1, int& k2, int& k3,
                                        float d, int k) {
    if (d < d3) {
        if (d < d2) {
            d3 = d2; k3 = k2;
            if (d < d1) { d2 = d1; k2 = k1; d1 = d; k1 = k; }
            else        { d2 = d;  k2 = k; }
        } else { d3 = d; k3 = k; }
    }
}

__device__ __forceinline__ float exact_dist(const float4* zv, const float* crow_f,
                                            float nrm) {
    const float4* crow = reinterpret_cast<const float4*>(crow_f);
    float s0 = 0.f, s1 = 0.f, s2 = 0.f, s3 = 0.f;
    #pragma unroll
    for (int i = 0; i < 16; i++) {
        float4 c = crow[i]; float4 z = zv[i];
        s0 = fmaf(z.x, c.x, s0); s1 = fmaf(z.y, c.y, s1);
        s2 = fmaf(z.z, c.z, s2); s3 = fmaf(z.w, c.w, s3);
    }
    return fmaf(-2.0f, (s0 + s1) + (s2 + s3), nrm);
}

// ---------------- prep: split codebook to fp16 hi|lo + norms ----------------

__global__ void prep_kernel(const float* __restrict__ cb) {
    const int k = threadIdx.x;
    if (k >= KC) return;
    const float4* row = reinterpret_cast<const float4*>(cb + (size_t)k * DQ);
    uint32_t* dst = reinterpret_cast<uint32_t*>(g_cbpack + (size_t)k * ROWB);
    float s0 = 0.f, s1 = 0.f, s2 = 0.f, s3 = 0.f;
    #pragma unroll
    for (int i = 0; i < 16; i++) {
        float4 f = row[i];
        s0 = fmaf(f.x, f.x, s0); s1 = fmaf(f.y, f.y, s1);
        s2 = fmaf(f.z, f.z, s2); s3 = fmaf(f.w, f.w, s3);
        __half hx = __float2half_rn(f.x), hy = __float2half_rn(f.y);
        __half hz = __float2half_rn(f.z), hw = __float2half_rn(f.w);
        dst[2*i]       = pack2(hx, hy);
        dst[2*i + 1]   = pack2(hz, hw);
        dst[32 + 2*i]     = pack2(__float2half_rn(f.x - __half2float(hx)),
                                  __float2half_rn(f.y - __half2float(hy)));
        dst[32 + 2*i + 1] = pack2(__float2half_rn(f.z - __half2float(hz)),
                                  __float2half_rn(f.w - __half2float(hw)));
    }
    g_cnorm[k] = (s0 + s1) + (s2 + s3);
}

// ---------------- main ----------------

__global__ __launch_bounds__(THREADS, 1)
void vq_main(const float* __restrict__ ze,
             const float* __restrict__ cb,
             float* __restrict__ out) {
    extern __shared__ char smem[];
    float* scn = reinterpret_cast<float*>(smem + PACK_BYTES);

    // Cooperative copy: packed codebook + norms -> SMEM.
    {
        const uint4* src = reinterpret_cast<const uint4*>(g_cbpack);
        uint4* dst = reinterpret_cast<uint4*>(smem);
        for (int i = threadIdx.x; i < PACK_BYTES / 16; i += THREADS) dst[i] = src[i];
        for (int i = threadIdx.x; i < KC; i += THREADS) scn[i] = g_cnorm[i];
    }

    const int tid  = threadIdx.x;
    const int w    = tid >> 5;
    const int lane = tid & 31;
    const int g    = lane >> 2;     // group 0..7
    const int t    = lane & 3;      // thread-in-group
    const int row_base = blockIdx.x * MROWS + w * 16;   // warp covers 16 rows

    // A fragments (1 m-tile of 16 rows, 4 k-tiles): Ah/Al[kt][reg]
    // reg mapping: idx = 2*h + rr  (h: k-half 0-7/8-15, rr: row g / g+8)
    uint32_t Ah[4][4], Al[4][4];
    #pragma unroll
    for (int kt = 0; kt < 4; kt++)
        #pragma unroll
        for (int h = 0; h < 2; h++)
            #pragma unroll
            for (int rr = 0; rr < 2; rr++) {
                const int row = row_base + g + 8 * rr;
                const int col = kt * 16 + h * 8 + 2 * t;
                float2 f = *reinterpret_cast<const float2*>(ze + (size_t)row * DQ + col);
                __half hx = __float2half_rn(f.x), hy = __float2half_rn(f.y);
                Ah[kt][2*h + rr] = pack2(hx, hy);
                Al[kt][2*h + rr] = pack2(__float2half_rn(f.x - __half2float(hx)),
                                         __float2half_rn(f.y - __half2float(hy)));
            }
    __syncthreads();

    // Running top-3 for the 2 rows this thread sees (slot0: row g, slot1: g+8)
    float td1[2], td2[2], td3[2];
    int   tk1[2], tk2[2], tk3[2];
    #pragma unroll
    for (int s = 0; s < 2; s++) {
        td1[s] = td2[s] = td3[s] = 3.4e38f;
        tk1[s] = tk2[s] = tk3[s] = 0;
    }

    const uint32_t smem_u = smem_u32(smem);
    const int      brow = ((lane >> 4) & 1) * 8 + (lane & 7);
    const uint32_t koff = ((lane >> 3) & 1) * 16;

    #pragma unroll 1
    for (int c = 0; c < KC / 16; c++) {
        const int n0 = c * 16;
        const uint32_t bbase = smem_u + (uint32_t)(n0 + brow) * ROWB + koff;

        float acc[2][4];
        #pragma unroll
        for (int nt = 0; nt < 2; nt++)
            #pragma unroll
            for (int q = 0; q < 4; q++) acc[nt][q] = 0.f;

        uint32_t B[4][4];
        // c_hi: seg0 (z_hi) + seg2 (z_lo)
        #pragma unroll
        for (int kt = 0; kt < 4; kt++)
            LDSM4(B[kt][0], B[kt][1], B[kt][2], B[kt][3], bbase + kt * 32);
        #pragma unroll
        for (int kt = 0; kt < 4; kt++) {
            MMA16816(acc[0][0], acc[0][1], acc[0][2], acc[0][3],
                     Ah[kt][0], Ah[kt][1], Ah[kt][2], Ah[kt][3], B[kt][0], B[kt][1]);
            MMA16816(acc[1][0], acc[1][1], acc[1][2], acc[1][3],
                     Ah[kt][0], Ah[kt][1], Ah[kt][2], Ah[kt][3], B[kt][2], B[kt][3]);
        }
        #pragma unroll
        for (int kt = 0; kt < 4; kt++) {
            MMA16816(acc[0][0], acc[0][1], acc[0][2], acc[0][3],
                     Al[kt][0], Al[kt][1], Al[kt][2], Al[kt][3], B[kt][0], B[kt][1]);
            MMA16816(acc[1][0], acc[1][1], acc[1][2], acc[1][3],
                     Al[kt][0], Al[kt][1], Al[kt][2], Al[kt][3], B[kt][2], B[kt][3]);
        }
        // c_lo: seg1 (z_hi)
        #pragma unroll
        for (int kt = 0; kt < 4; kt++)
            LDSM4(B[kt][0], B[kt][1], B[kt][2], B[kt][3], bbase + 128 + kt * 32);
        #pragma unroll
        for (int kt = 0; kt < 4; kt++) {
            MMA16816(acc[0][0], acc[0][1], acc[0][2], acc[0][3],
                     Ah[kt][0], Ah[kt][1], Ah[kt][2], Ah[kt][3], B[kt][0], B[kt][1]);
            MMA16816(acc[1][0], acc[1][1], acc[1][2], acc[1][3],
                     Ah[kt][0], Ah[kt][1], Ah[kt][2], Ah[kt][3], B[kt][2], B[kt][3]);
        }

        // epilogue: 8 candidates (2 n-tiles x 2 rows x 2 cols)
        const float2 cn0 = *reinterpret_cast<const float2*>(&scn[n0 + 2 * t]);
        const float2 cn1 = *reinterpret_cast<const float2*>(&scn[n0 + 8 + 2 * t]);
        #pragma unroll
        for (int nt = 0; nt < 2; nt++) {
            const float cA = nt ? cn1.x : cn0.x;
            const float cB = nt ? cn1.y : cn0.y;
            const int colA = n0 + nt * 8 + 2 * t;
            insert3(td1[0], td2[0], td3[0], tk1[0], tk2[0], tk3[0],
                    fmaf(-2.f, acc[nt][0], cA), colA);
            insert3(td1[0], td2[0], td3[0], tk1[0], tk2[0], tk3[0],
                    fmaf(-2.f, acc[nt][1], cB), colA + 1);
            insert3(td1[1], td2[1], td3[1], tk1[1], tk2[1], tk3[1],
                    fmaf(-2.f, acc[nt][2], cA), colA);
            insert3(td1[1], td2[1], td3[1], tk1[1], tk2[1], tk3[1],
                    fmaf(-2.f, acc[nt][3], cB), colA + 1);
        }
    }

    // Cross-lane merge: lanes 4g..4g+3 hold disjoint column slices of rows
    // g and g+8. Butterfly over xor 1, 2.
    #pragma unroll
    for (int xo = 1; xo <= 2; xo <<= 1) {
        #pragma unroll
        for (int s = 0; s < 2; s++) {
            float o1 = __shfl_xor_sync(0xFFFFFFFFu, td1[s], xo);
            float o2 = __shfl_xor_sync(0xFFFFFFFFu, td2[s], xo);
            float o3 = __shfl_xor_sync(0xFFFFFFFFu, td3[s], xo);
            int   q1 = __shfl_xor_sync(0xFFFFFFFFu, tk1[s], xo);
            int   q2 = __shfl_xor_sync(0xFFFFFFFFu, tk2[s], xo);
            int   q3 = __shfl_xor_sync(0xFFFFFFFFu, tk3[s], xo);
            insert3(td1[s], td2[s], td3[s], tk1[s], tk2[s], tk3[s], o1, q1);
            insert3(td1[s], td2[s], td3[s], tk1[s], tk2[s], tk3[s], o2, q2);
            insert3(td1[s], td2[s], td3[s], tk1[s], tk2[s], tk3[s], o3, q3);
        }
    }

    // Resolution: lane 4g+t owns row g+8t for t<2.
    int kw = 0;
    if (t < 2) {
        const int my_row = row_base + g + 8 * t;
        const float rd1 = td1[t], rd2 = td2[t], rd3 = td3[t];
        const int   rk1 = tk1[t], rk2 = tk2[t];
        kw = rk1;
        if (rd3 - rd1 < DELTA) {
            float4 zv[16];
            const float4* zp = reinterpret_cast<const float4*>(ze + (size_t)my_row * DQ);
            #pragma unroll
            for (int i = 0; i < 16; i++) zv[i] = zp[i];
            float best = 3.4e38f; int bk = 0;
            for (int k = 0; k < KC; k++) {
                const float d = exact_dist(zv, cb + (size_t)k * DQ, scn[k]);
                if (d < best) { best = d; bk = k; }
            }
            kw = bk;
        } else if (rd2 - rd1 < DELTA) {
            float4 zv[16];
            const float4* zp = reinterpret_cast<const float4*>(ze + (size_t)my_row * DQ);
            #pragma unroll
            for (int i = 0; i < 16; i++) zv[i] = zp[i];
            const float e1 = exact_dist(zv, cb + (size_t)rk1 * DQ, scn[rk1]);
            const float e2 = exact_dist(zv, cb + (size_t)rk2 * DQ, scn[rk2]);
            if (e2 < e1 || (e2 == e1 && rk2 < rk1)) kw = rk2;
        }
    }

    // Coalesced gather/write: warp streams its 16 rows.
    #pragma unroll 1
    for (int r = 0; r < 16; r++) {
        const int src_lane = 4 * (r & 7) + (r >> 3);   // owner of warp-row r
        const int kk = __shfl_sync(0xFFFFFFFFu, kw, src_lane);
        const float2 v = reinterpret_cast<const float2*>(cb + (size_t)kk * DQ)[lane];
        reinterpret_cast<float2*>(out + (size_t)(row_base + r) * DQ)[lane] = v;
    }
}

extern "C" void kernel_launch(void* const* d_in, const int* in_sizes, int n_in,
                              void* d_out, int out_size) {
    const float* ze = (const float*)d_in[0];
    const float* cb = (const float*)d_in[1];
    float* out = (float*)d_out;
    const int n_tokens = in_sizes[0] / DQ;
    const int grid = n_tokens / MROWS;   // 2048

    prep_kernel<<<1, KC>>>(cb);
    cudaFuncSetAttribute(vq_main,
                         cudaFuncAttributeMaxDynamicSharedMemorySize, SMEM_TOTAL);
    vq_main<<<grid, THREADS, SMEM_TOTAL>>>(ze, cb, out);
}